// round 8
// baseline (speedup 1.0000x reference)
#include <cuda_runtime.h>
#include <cuda_fp16.h>
#include <cstdint>

// Problem constants
#define NROWS   4096
#define INFEAT  4096
#define OUTFEAT 4096
#define NCODE   256
#define KLEAF   16
#define KGLOB   4096
// Aggregation tiling
#define TO      128
#define TN      256
#define THREADS 512
#define CCH     8
#define NCHUNK  (NCODE / CCH)      // 32
#define BUFB    32768              // bytes per staging buffer
#define AGG_SMEM (2 * BUFB)        // 64 KB

// Static device scratch
__device__ __align__(16) unsigned char g_codes[NROWS * NCODE];          // 1 MB
__device__ __align__(16) __half        g_lutT[(size_t)KGLOB * OUTFEAT]; // 32 MB [k][o]

// ---------------------------------------------------------------- helpers
__device__ __forceinline__ uint32_t smem_u32(const void* p) {
    uint32_t a;
    asm("{ .reg .u64 t; cvta.to.shared.u64 t, %1; cvt.u32.u64 %0, t; }"
        : "=r"(a) : "l"(p));
    return a;
}
__device__ __forceinline__ void cp_async16(uint32_t s, const void* g) {
    asm volatile("cp.async.cg.shared.global [%0], [%1], 16;"
                 :: "r"(s), "l"(g) : "memory");
}
__device__ __forceinline__ void cp_commit() {
    asm volatile("cp.async.commit_group;" ::: "memory");
}
__device__ __forceinline__ void cp_wait0() {
    asm volatile("cp.async.wait_group 0;" ::: "memory");
}
__device__ __forceinline__ void cp_wait1() {
    asm volatile("cp.async.wait_group 1;" ::: "memory");
}

// ---------------------------------------------------------------- encode
__global__ void __launch_bounds__(NCODE) encode_kernel(
    const float* __restrict__ input,
    const int*   __restrict__ dims,
    const float* __restrict__ thr)
{
    const int n = blockIdx.x;
    const int c = threadIdx.x;
    const int4 d4 = *reinterpret_cast<const int4*>(dims + c * 4);
    const float* row = input + (size_t)n * INFEAT;
    const float x0 = __ldg(row + d4.x);
    const float x1 = __ldg(row + d4.y);
    const float x2 = __ldg(row + d4.z);
    const float x3 = __ldg(row + d4.w);
    const float* t = thr + c * 15;
    int i = 1;
    i = 2 * i + (x0 > __ldg(t + i - 1) ? 1 : 0);
    i = 2 * i + (x1 > __ldg(t + i - 1) ? 1 : 0);
    i = 2 * i + (x2 > __ldg(t + i - 1) ? 1 : 0);
    i = 2 * i + (x3 > __ldg(t + i - 1) ? 1 : 0);
    g_codes[n * NCODE + c] = (unsigned char)(i - 16);
}

// ---------------------------------------------------------------- transpose
// g_lutT[k][o] = half(lut[o][k])
__global__ void __launch_bounds__(256) transpose_kernel(
    const float* __restrict__ lut)
{
    __shared__ __half tile[64][66];

    const int k0 = blockIdx.x * 64;
    const int o0 = blockIdx.y * 64;
    const int tid = threadIdx.x;

#pragma unroll
    for (int j = 0; j < 16; ++j) {
        const int flat = j * 256 + tid;
        const int o = flat >> 6;
        const int k = flat & 63;
        tile[k][o] = __float2half(
            __ldg(lut + (size_t)(o0 + o) * KGLOB + k0 + k));
    }
    __syncthreads();
#pragma unroll
    for (int j = 0; j < 16; ++j) {
        const int flat = j * 256 + tid;
        const int k = flat >> 6;
        const int o = flat & 63;
        g_lutT[(size_t)(k0 + k) * OUTFEAT + o0 + o] = tile[k][o];
    }
}

// ---------------------------------------------------------------- agg
// Block: 512 threads (16 warps), tile TO=128 outputs x TN=256 rows.
// Double-buffered cp.async staging of lut chunks [128 idx][128 half].
// Gather: two independent LDS.32 per (row, cb) — each one conflict-free
// 128B wavefront (the narrow-load rule from R2/R7 post-mortems).
// Lane owns outputs {2*lane, 2*lane+1, 64+2*lane, 64+2*lane+1}.
// half2 group-8 accumulation, fp32 fold per chunk.
__global__ void __launch_bounds__(THREADS, 1) agg_kernel(float* __restrict__ out)
{
    extern __shared__ __align__(16) char smem[];
    const uint32_t sb = smem_u32(smem);

    const int o0   = blockIdx.x * TO;
    const int n0   = blockIdx.y * TN;
    const int tid  = threadIdx.x;
    const int warp = tid >> 5;
    const int lane = tid & 31;
    const int rowbase = n0 + warp * 16;

    const uint32_t lane_byte = (uint32_t)lane * 4;   // LDS.32 base in idx-row

    float acc[16][4];
#pragma unroll
    for (int t = 0; t < 16; ++t)
#pragma unroll
        for (int j = 0; j < 4; ++j) acc[t][j] = 0.0f;

    // Stage chunk ch into buffer (2048 x 16B, 4 per thread, coalesced)
#define STAGE(ch, bufbase) do {                                                \
    const int _c0k = (ch) * CCH * KLEAF;                                       \
    _Pragma("unroll")                                                          \
    for (int _i = 0; _i < 4; ++_i) {                                           \
        const int _flat = _i * THREADS + tid;      /* 0..2047 */               \
        const int _idx  = _flat >> 4;                                          \
        const int _pos  = _flat & 15;                                          \
        cp_async16((bufbase) + (uint32_t)_flat * 16,                           \
                   g_lutT + (size_t)(_c0k + _idx) * OUTFEAT + o0 + _pos * 8);  \
    }                                                                          \
    cp_commit();                                                               \
} while (0)

    // Prologue
    STAGE(0, sb);

    for (int ch = 0; ch < NCHUNK; ++ch) {
        __syncthreads();               // all readers done with the buffer being refilled
        if (ch + 1 < NCHUNK) {
            STAGE(ch + 1, sb + (uint32_t)((ch + 1) & 1) * BUFB);
            cp_wait1();                // chunk ch complete, ch+1 in flight
        } else {
            cp_wait0();
        }
        __syncthreads();               // fills visible to all warps

        const uint32_t gbase = sb + (uint32_t)(ch & 1) * BUFB + lane_byte;
        const int cb0 = ch * CCH;

#pragma unroll
        for (int t = 0; t < 16; ++t) {
            const int row = rowbase + t;
            const uint2 cw = *reinterpret_cast<const uint2*>(
                g_codes + (size_t)row * NCODE + cb0);   // warp-uniform
            __half2 h01 = __float2half2_rn(0.0f);
            __half2 h23 = __float2half2_rn(0.0f);
#pragma unroll
            for (int cc = 0; cc < 8; ++cc) {
                const unsigned int w = (cc < 4) ? cw.x : cw.y;
                // byte (cc&3) of w placed at result byte1 => code*256
                const unsigned int c256 =
                    __byte_perm(w, 0u, 0x4404u | (((unsigned)cc & 3u) << 4));
                const uint32_t a = gbase + (uint32_t)cc * 4096u + c256;
                uint32_t v0, v1;
                asm volatile("ld.shared.u32 %0, [%1];"
                             : "=r"(v0) : "r"(a));
                asm volatile("ld.shared.u32 %0, [%1];"
                             : "=r"(v1) : "r"(a + 128u));
                h01 = __hadd2(h01, *reinterpret_cast<const __half2*>(&v0));
                h23 = __hadd2(h23, *reinterpret_cast<const __half2*>(&v1));
            }
            const float2 f0 = __half22float2(h01);
            const float2 f1 = __half22float2(h23);
            acc[t][0] += f0.x;
            acc[t][1] += f0.y;
            acc[t][2] += f1.x;
            acc[t][3] += f1.y;
        }
    }

    // Store: coalesced float2 writes
#pragma unroll
    for (int t = 0; t < 16; ++t) {
        float* orow = out + (size_t)(rowbase + t) * OUTFEAT + o0;
        float2 a; a.x = acc[t][0]; a.y = acc[t][1];
        float2 b; b.x = acc[t][2]; b.y = acc[t][3];
        *reinterpret_cast<float2*>(orow + 2 * lane)      = a;
        *reinterpret_cast<float2*>(orow + 64 + 2 * lane) = b;
    }
}

// ---------------------------------------------------------------- launch
extern "C" void kernel_launch(void* const* d_in, const int* in_sizes, int n_in,
                              void* d_out, int out_size)
{
    const float* input = (const float*)d_in[0];
    const int*   dims  = (const int*)  d_in[1];
    const float* thr   = (const float*)d_in[3];
    const float* lut   = (const float*)d_in[5];
    float*       out   = (float*)d_out;
    (void)in_sizes; (void)n_in; (void)out_size;

    cudaFuncSetAttribute(agg_kernel,
                         cudaFuncAttributeMaxDynamicSharedMemorySize, AGG_SMEM);

    encode_kernel<<<NROWS, NCODE>>>(input, dims, thr);

    dim3 tgrid(KGLOB / 64, OUTFEAT / 64);
    transpose_kernel<<<tgrid, 256>>>(lut);

    dim3 grid(OUTFEAT / TO, NROWS / TN);
    agg_kernel<<<grid, THREADS, AGG_SMEM>>>(out);
}

// round 9
// speedup vs baseline: 1.0652x; 1.0652x over previous
#include <cuda_runtime.h>
#include <cuda_fp16.h>
#include <cstdint>

// Problem constants
#define NROWS   4096
#define INFEAT  4096
#define OUTFEAT 4096
#define NCODE   256
#define KLEAF   16
#define KGLOB   4096
// Aggregation tiling
#define TO      128
#define TN      128
#define THREADS 256
#define CCH     8
#define NCHUNK  (NCODE / CCH)      // 32
#define BUFB    32768              // bytes per staging buffer
#define NBUF    3
#define AGG_SMEM (NBUF * BUFB)     // 96 KB

// Static device scratch
__device__ __align__(16) unsigned char g_codes[NROWS * NCODE];          // 1 MB
__device__ __align__(16) __half        g_lutT[(size_t)KGLOB * OUTFEAT]; // 32 MB [k][o]

// ---------------------------------------------------------------- helpers
__device__ __forceinline__ uint32_t smem_u32(const void* p) {
    uint32_t a;
    asm("{ .reg .u64 t; cvta.to.shared.u64 t, %1; cvt.u32.u64 %0, t; }"
        : "=r"(a) : "l"(p));
    return a;
}
__device__ __forceinline__ void cp_async16(uint32_t s, const void* g) {
    asm volatile("cp.async.cg.shared.global [%0], [%1], 16;"
                 :: "r"(s), "l"(g) : "memory");
}
__device__ __forceinline__ void cp_commit() {
    asm volatile("cp.async.commit_group;" ::: "memory");
}
template <int N>
__device__ __forceinline__ void cp_wait() {
    asm volatile("cp.async.wait_group %0;" :: "n"(N) : "memory");
}

// ---------------------------------------------------------------- encode
__global__ void __launch_bounds__(NCODE) encode_kernel(
    const float* __restrict__ input,
    const int*   __restrict__ dims,
    const float* __restrict__ thr)
{
    const int n = blockIdx.x;
    const int c = threadIdx.x;
    const int4 d4 = *reinterpret_cast<const int4*>(dims + c * 4);
    const float* row = input + (size_t)n * INFEAT;
    const float x0 = __ldg(row + d4.x);
    const float x1 = __ldg(row + d4.y);
    const float x2 = __ldg(row + d4.z);
    const float x3 = __ldg(row + d4.w);
    const float* t = thr + c * 15;
    int i = 1;
    i = 2 * i + (x0 > __ldg(t + i - 1) ? 1 : 0);
    i = 2 * i + (x1 > __ldg(t + i - 1) ? 1 : 0);
    i = 2 * i + (x2 > __ldg(t + i - 1) ? 1 : 0);
    i = 2 * i + (x3 > __ldg(t + i - 1) ? 1 : 0);
    g_codes[n * NCODE + c] = (unsigned char)(i - 16);
}

// ---------------------------------------------------------------- transpose
// g_lutT[k][o] = half(lut[o][k])
__global__ void __launch_bounds__(256) transpose_kernel(
    const float* __restrict__ lut)
{
    __shared__ __half tile[64][66];

    const int k0 = blockIdx.x * 64;
    const int o0 = blockIdx.y * 64;
    const int tid = threadIdx.x;

#pragma unroll
    for (int j = 0; j < 16; ++j) {
        const int flat = j * 256 + tid;
        const int o = flat >> 6;
        const int k = flat & 63;
        tile[k][o] = __float2half(
            __ldg(lut + (size_t)(o0 + o) * KGLOB + k0 + k));
    }
    __syncthreads();
#pragma unroll
    for (int j = 0; j < 16; ++j) {
        const int flat = j * 256 + tid;
        const int k = flat >> 6;
        const int o = flat & 63;
        g_lutT[(size_t)(k0 + k) * OUTFEAT + o0 + o] = tile[k][o];
    }
}

// ---------------------------------------------------------------- agg
// Block: 256 threads (8 warps), occ 2 -> 16 warps/SM, two independent
// barrier domains per SM (the R6 property that beat the 512-thread variants).
// Staging: cp.async, 3 buffers, prefetch distance 2 (wait_group slack).
// Gather: two independent LDS.32 per (row, cb), each one conflict-free
// 128B wavefront. half2 group-8 accumulation (chains seeded from first
// load -> identical arithmetic to the 412us champion), fp32 fold per chunk.
__global__ void __launch_bounds__(THREADS, 2) agg_kernel(float* __restrict__ out)
{
    extern __shared__ __align__(16) char smem[];
    const uint32_t sb = smem_u32(smem);

    const int o0   = blockIdx.x * TO;
    const int n0   = blockIdx.y * TN;
    const int tid  = threadIdx.x;
    const int warp = tid >> 5;
    const int lane = tid & 31;
    const int rowbase = n0 + warp * 16;

    const uint32_t lane_byte = (uint32_t)lane * 4;   // LDS.32 base in idx-row

    float acc[16][4];
#pragma unroll
    for (int t = 0; t < 16; ++t)
#pragma unroll
        for (int j = 0; j < 4; ++j) acc[t][j] = 0.0f;

    // Stage chunk ch into buffer (2048 x 16B, 8 per thread, coalesced)
#define STAGE(ch, bufbase) do {                                                \
    const int _c0k = (ch) * CCH * KLEAF;                                       \
    _Pragma("unroll")                                                          \
    for (int _i = 0; _i < 8; ++_i) {                                           \
        const int _flat = _i * THREADS + tid;      /* 0..2047 */               \
        const int _idx  = _flat >> 4;                                          \
        const int _pos  = _flat & 15;                                          \
        cp_async16((bufbase) + (uint32_t)_flat * 16,                           \
                   g_lutT + (size_t)(_c0k + _idx) * OUTFEAT + o0 + _pos * 8);  \
    }                                                                          \
    cp_commit();                                                               \
} while (0)

    // Prologue: prefetch chunks 0 and 1
    STAGE(0, sb);
    STAGE(1, sb + BUFB);

    for (int ch = 0; ch < NCHUNK; ++ch) {
        // Prefetch ch+2 (buffer (ch+2)%3 == (ch-1)%3, whose readers finished
        // at the barrier that ended iteration ch-1)
        if (ch + 2 < NCHUNK)
            STAGE(ch + 2, sb + (uint32_t)((ch + 2) % NBUF) * BUFB);

        // Wait until chunk ch's group has landed
        if (ch + 2 < NCHUNK)      cp_wait<2>();
        else if (ch + 1 < NCHUNK) cp_wait<1>();
        else                      cp_wait<0>();
        __syncthreads();               // fills visible to all warps

        const uint32_t gbase = sb + (uint32_t)(ch % NBUF) * BUFB + lane_byte;
        const int cb0 = ch * CCH;

#pragma unroll
        for (int t = 0; t < 16; ++t) {
            const int row = rowbase + t;
            const uint2 cw = *reinterpret_cast<const uint2*>(
                g_codes + (size_t)row * NCODE + cb0);   // warp-uniform
            __half2 h01, h23;
#pragma unroll
            for (int cc = 0; cc < 8; ++cc) {
                const unsigned int w = (cc < 4) ? cw.x : cw.y;
                // byte (cc&3) of w placed at result byte1 => code*256
                const unsigned int c256 =
                    __byte_perm(w, 0u, 0x4404u | (((unsigned)cc & 3u) << 4));
                const uint32_t a = gbase + (uint32_t)cc * 4096u + c256;
                uint32_t v0, v1;
                asm volatile("ld.shared.u32 %0, [%1];" : "=r"(v0) : "r"(a));
                asm volatile("ld.shared.u32 %0, [%1];" : "=r"(v1) : "r"(a + 128u));
                const __half2 hv0 = *reinterpret_cast<const __half2*>(&v0);
                const __half2 hv1 = *reinterpret_cast<const __half2*>(&v1);
                if (cc == 0) { h01 = hv0; h23 = hv1; }
                else         { h01 = __hadd2(h01, hv0); h23 = __hadd2(h23, hv1); }
            }
            const float2 f0 = __half22float2(h01);
            const float2 f1 = __half22float2(h23);
            acc[t][0] += f0.x;
            acc[t][1] += f0.y;
            acc[t][2] += f1.x;
            acc[t][3] += f1.y;
        }
        __syncthreads();               // readers done before buffer is restaged
    }

    // Store: coalesced float2 writes
#pragma unroll
    for (int t = 0; t < 16; ++t) {
        float* orow = out + (size_t)(rowbase + t) * OUTFEAT + o0;
        float2 a; a.x = acc[t][0]; a.y = acc[t][1];
        float2 b; b.x = acc[t][2]; b.y = acc[t][3];
        *reinterpret_cast<float2*>(orow + 2 * lane)      = a;
        *reinterpret_cast<float2*>(orow + 64 + 2 * lane) = b;
    }
}

// ---------------------------------------------------------------- launch
extern "C" void kernel_launch(void* const* d_in, const int* in_sizes, int n_in,
                              void* d_out, int out_size)
{
    const float* input = (const float*)d_in[0];
    const int*   dims  = (const int*)  d_in[1];
    const float* thr   = (const float*)d_in[3];
    const float* lut   = (const float*)d_in[5];
    float*       out   = (float*)d_out;
    (void)in_sizes; (void)n_in; (void)out_size;

    cudaFuncSetAttribute(agg_kernel,
                         cudaFuncAttributeMaxDynamicSharedMemorySize, AGG_SMEM);

    encode_kernel<<<NROWS, NCODE>>>(input, dims, thr);

    dim3 tgrid(KGLOB / 64, OUTFEAT / 64);
    transpose_kernel<<<tgrid, 256>>>(lut);

    dim3 grid(OUTFEAT / TO, NROWS / TN);
    agg_kernel<<<grid, THREADS, AGG_SMEM>>>(out);
}

// round 10
// speedup vs baseline: 1.1323x; 1.0630x over previous
#include <cuda_runtime.h>
#include <cuda_fp16.h>
#include <cstdint>

// Problem constants
#define NROWS   4096
#define INFEAT  4096
#define OUTFEAT 4096
#define NCODE   256
#define KLEAF   16
#define KGLOB   4096
// Aggregation tiling
#define TO      128
#define TN      128
#define THREADS 256
#define CCH     8
#define NCHUNK  (NCODE / CCH)      // 32
#define BUFB    32768              // bytes per staging buffer
#define NBUF    3
#define AGG_SMEM (NBUF * BUFB)     // 96 KB

// Static device scratch
__device__ __align__(16) unsigned char g_codes[NROWS * NCODE];          // 1 MB
__device__ __align__(16) __half        g_lutT[(size_t)KGLOB * OUTFEAT]; // 32 MB [k][o]

// ---------------------------------------------------------------- helpers
__device__ __forceinline__ uint32_t smem_u32(const void* p) {
    uint32_t a;
    asm("{ .reg .u64 t; cvta.to.shared.u64 t, %1; cvt.u32.u64 %0, t; }"
        : "=r"(a) : "l"(p));
    return a;
}
__device__ __forceinline__ void cp_async16(uint32_t s, const void* g) {
    asm volatile("cp.async.cg.shared.global [%0], [%1], 16;"
                 :: "r"(s), "l"(g) : "memory");
}
__device__ __forceinline__ void cp_commit() {
    asm volatile("cp.async.commit_group;" ::: "memory");
}
template <int N>
__device__ __forceinline__ void cp_wait() {
    asm volatile("cp.async.wait_group %0;" :: "n"(N) : "memory");
}

// ---------------------------------------------------------------- encode
__global__ void __launch_bounds__(NCODE) encode_kernel(
    const float* __restrict__ input,
    const int*   __restrict__ dims,
    const float* __restrict__ thr)
{
    const int n = blockIdx.x;
    const int c = threadIdx.x;
    const int4 d4 = *reinterpret_cast<const int4*>(dims + c * 4);
    const float* row = input + (size_t)n * INFEAT;
    const float x0 = __ldg(row + d4.x);
    const float x1 = __ldg(row + d4.y);
    const float x2 = __ldg(row + d4.z);
    const float x3 = __ldg(row + d4.w);
    const float* t = thr + c * 15;
    int i = 1;
    i = 2 * i + (x0 > __ldg(t + i - 1) ? 1 : 0);
    i = 2 * i + (x1 > __ldg(t + i - 1) ? 1 : 0);
    i = 2 * i + (x2 > __ldg(t + i - 1) ? 1 : 0);
    i = 2 * i + (x3 > __ldg(t + i - 1) ? 1 : 0);
    g_codes[n * NCODE + c] = (unsigned char)(i - 16);
}

// ---------------------------------------------------------------- transpose
// g_lutT[k][o] = half(lut[o][k])
__global__ void __launch_bounds__(256) transpose_kernel(
    const float* __restrict__ lut)
{
    __shared__ __half tile[64][66];

    const int k0 = blockIdx.x * 64;
    const int o0 = blockIdx.y * 64;
    const int tid = threadIdx.x;

#pragma unroll
    for (int j = 0; j < 16; ++j) {
        const int flat = j * 256 + tid;
        const int o = flat >> 6;
        const int k = flat & 63;
        tile[k][o] = __float2half(
            __ldg(lut + (size_t)(o0 + o) * KGLOB + k0 + k));
    }
    __syncthreads();
#pragma unroll
    for (int j = 0; j < 16; ++j) {
        const int flat = j * 256 + tid;
        const int k = flat >> 6;
        const int o = flat & 63;
        g_lutT[(size_t)(k0 + k) * OUTFEAT + o0 + o] = tile[k][o];
    }
}

// ---------------------------------------------------------------- agg
// Block: 256 threads (8 warps), occ 2. Tile: TO=128 outputs x TN=128 rows.
// Staging: cp.async, 3 buffers, prefetch distance 2, ONE barrier per chunk
// (STAGE of ch+2 moved after the barrier: its target buffer was last read
// in iteration ch-1, proven drained by that iteration's barrier).
// Gather: two independent LDS.32 per (row, cb), each a single conflict-free
// 128B wavefront. All 16 loads of a row issued before a depth-3 pairwise
// HADD2 tree (was a depth-8 serial chain), fp32 fold per chunk.
__global__ void __launch_bounds__(THREADS, 2) agg_kernel(float* __restrict__ out)
{
    extern __shared__ __align__(16) char smem[];
    const uint32_t sb = smem_u32(smem);

    const int o0   = blockIdx.x * TO;
    const int n0   = blockIdx.y * TN;
    const int tid  = threadIdx.x;
    const int warp = tid >> 5;
    const int lane = tid & 31;
    const int rowbase = n0 + warp * 16;

    const uint32_t lane_byte = (uint32_t)lane * 4;   // LDS.32 base in idx-row

    float acc[16][4];
#pragma unroll
    for (int t = 0; t < 16; ++t)
#pragma unroll
        for (int j = 0; j < 4; ++j) acc[t][j] = 0.0f;

    // Stage chunk ch into buffer (2048 x 16B, 8 per thread, coalesced)
#define STAGE(ch, bufbase) do {                                                \
    const int _c0k = (ch) * CCH * KLEAF;                                       \
    _Pragma("unroll")                                                          \
    for (int _i = 0; _i < 8; ++_i) {                                           \
        const int _flat = _i * THREADS + tid;      /* 0..2047 */               \
        const int _idx  = _flat >> 4;                                          \
        const int _pos  = _flat & 15;                                          \
        cp_async16((bufbase) + (uint32_t)_flat * 16,                           \
                   g_lutT + (size_t)(_c0k + _idx) * OUTFEAT + o0 + _pos * 8);  \
    }                                                                          \
    cp_commit();                                                               \
} while (0)

    // Prologue: prefetch chunks 0 and 1
    STAGE(0, sb);
    STAGE(1, sb + BUFB);

    for (int ch = 0; ch < NCHUNK; ++ch) {
        // In-flight groups here: {ch, ch+1} -> wait until ch has landed
        if (ch + 1 < NCHUNK) cp_wait<1>();
        else                 cp_wait<0>();
        __syncthreads();   // (a) all slices of ch visible; (b) everyone done
                           //     reading buffer (ch-1)%3 == (ch+2)%3

        if (ch + 2 < NCHUNK)
            STAGE(ch + 2, sb + (uint32_t)((ch + 2) % NBUF) * BUFB);

        const uint32_t gbase = sb + (uint32_t)(ch % NBUF) * BUFB + lane_byte;
        const int cb0 = ch * CCH;

#pragma unroll
        for (int t = 0; t < 16; ++t) {
            const int row = rowbase + t;
            const uint2 cw = *reinterpret_cast<const uint2*>(
                g_codes + (size_t)row * NCODE + cb0);   // warp-uniform

            uint32_t v0[8], v1[8];
#pragma unroll
            for (int cc = 0; cc < 8; ++cc) {
                const unsigned int w = (cc < 4) ? cw.x : cw.y;
                // byte (cc&3) of w placed at result byte1 => code*256
                const unsigned int c256 =
                    __byte_perm(w, 0u, 0x4404u | (((unsigned)cc & 3u) << 4));
                const uint32_t a = gbase + (uint32_t)cc * 4096u + c256;
                asm volatile("ld.shared.u32 %0, [%1];" : "=r"(v0[cc]) : "r"(a));
                asm volatile("ld.shared.u32 %0, [%1];" : "=r"(v1[cc]) : "r"(a + 128u));
            }
#define H2(x) (*reinterpret_cast<const __half2*>(&(x)))
            // Pairwise reduction, depth 3
            __half2 p0 = __hadd2(H2(v0[0]), H2(v0[1]));
            __half2 p1 = __hadd2(H2(v0[2]), H2(v0[3]));
            __half2 p2 = __hadd2(H2(v0[4]), H2(v0[5]));
            __half2 p3 = __hadd2(H2(v0[6]), H2(v0[7]));
            __half2 q0 = __hadd2(H2(v1[0]), H2(v1[1]));
            __half2 q1 = __hadd2(H2(v1[2]), H2(v1[3]));
            __half2 q2 = __hadd2(H2(v1[4]), H2(v1[5]));
            __half2 q3 = __hadd2(H2(v1[6]), H2(v1[7]));
            const __half2 h01 = __hadd2(__hadd2(p0, p1), __hadd2(p2, p3));
            const __half2 h23 = __hadd2(__hadd2(q0, q1), __hadd2(q2, q3));
#undef H2
            const float2 f0 = __half22float2(h01);
            const float2 f1 = __half22float2(h23);
            acc[t][0] += f0.x;
            acc[t][1] += f0.y;
            acc[t][2] += f1.x;
            acc[t][3] += f1.y;
        }
    }

    // Store: coalesced float2 writes
#pragma unroll
    for (int t = 0; t < 16; ++t) {
        float* orow = out + (size_t)(rowbase + t) * OUTFEAT + o0;
        float2 a; a.x = acc[t][0]; a.y = acc[t][1];
        float2 b; b.x = acc[t][2]; b.y = acc[t][3];
        *reinterpret_cast<float2*>(orow + 2 * lane)      = a;
        *reinterpret_cast<float2*>(orow + 64 + 2 * lane) = b;
    }
}

// ---------------------------------------------------------------- launch
extern "C" void kernel_launch(void* const* d_in, const int* in_sizes, int n_in,
                              void* d_out, int out_size)
{
    const float* input = (const float*)d_in[0];
    const int*   dims  = (const int*)  d_in[1];
    const float* thr   = (const float*)d_in[3];
    const float* lut   = (const float*)d_in[5];
    float*       out   = (float*)d_out;
    (void)in_sizes; (void)n_in; (void)out_size;

    cudaFuncSetAttribute(agg_kernel,
                         cudaFuncAttributeMaxDynamicSharedMemorySize, AGG_SMEM);

    encode_kernel<<<NROWS, NCODE>>>(input, dims, thr);

    dim3 tgrid(KGLOB / 64, OUTFEAT / 64);
    transpose_kernel<<<tgrid, 256>>>(lut);

    dim3 grid(OUTFEAT / TO, NROWS / TN);
    agg_kernel<<<grid, THREADS, AGG_SMEM>>>(out);
}